// round 14
// baseline (speedup 1.0000x reference)
#include <cuda_runtime.h>
#include <stdint.h>

#define BATCH   32
#define NBOX    8400
#define NCLS    80
#define NC      (NBOX*NCLS)       // 672000
#define TOPK    1024
#define CAP     2048
#define CAP1    8192
#define MAXDET  300
#define SCORE_T 0.001f
#define IOU_T   0.7f
#define T0      0.995f
#define V4_PER_BATCH (NC/4)             // 168000
#define TOTAL_V4 (BATCH*V4_PER_BATCH)   // 5376000
#define SCAN_BLOCKS (TOTAL_V4/2048)     // 2625 (chunks of 2048 float4)
#define GRID    148                     // <= SM count: all CTAs resident (safe spin barrier)

// ---- dynamic smem layout (bytes), all 8-aligned ----------------------------
#define SM_SLOT    0                      // 2048 * 8 = 16384  (bucket-grouped keys)
#define SM_SORT    16384                  // 1024 * 8 = 8192   -> 24576
#define SM_CNT     24576                  // 2048 * 4 = 8192   -> 32768 (cnt+start = 4096 words, contiguous for fallback)
#define SM_START   32768                  // 2048 * 4 = 8192   -> 40960
#define SM_FILL    40960                  // 2048 * 4 = 8192   -> 49152
#define SM_Y1      49152                  // 1024 * 4
#define SM_X1      53248
#define SM_Y2      57344
#define SM_X2      61440
#define SM_AREA    65536                  // -> 69632
#define SM_CLSCNT  69632                  // 80*4 -> 69952
#define SM_CLSOFF  69952                  // 80*4 -> 70272
#define SM_CLSFILL 70272                  // 80*4 -> 70592
#define SM_CLSLIST 70592                  // 1024*2 -> 72640
#define SM_ALIVE   72640                  // 1024 -> 73664
#define SM_WSCAN   73664                  // 128 -> 73792
#define SM_TOTAL   73792

// ---------------- device scratch (static) -----------------------------------
__device__ int                g_c1[BATCH];            // reset at end of each run
__device__ unsigned long long g_cand1[BATCH][CAP1];
__device__ unsigned           g_arrive;               // self-resetting
__device__ volatile unsigned  g_gen;                  // monotone generation

// ---------------- phase 1 helper: scan one 2048-float4 chunk ----------------
__device__ __forceinline__ void scan_block(const float4* __restrict__ p, int bb,
                                           int tid, int lane) {
    size_t blockBase = (size_t)bb * 2048;

    float4 v[8];
#pragma unroll
    for (int k = 0; k < 8; k++)
        v[k] = p[blockBase + (size_t)k * 256 + (tid & 255)];

    int b0 = (int)(blockBase / V4_PER_BATCH);
    int bL = (int)((blockBase + 2047) / V4_PER_BATCH);
    bool uniformB = (b0 == bL);

    int cnt = 0;
#pragma unroll
    for (int k = 0; k < 8; k++) {
        float a[4] = {v[k].x, v[k].y, v[k].z, v[k].w};
#pragma unroll
        for (int c = 0; c < 4; c++) cnt += (a[c] > T0) ? 1 : 0;
    }

    if (uniformB) {
        int incl = cnt;
#pragma unroll
        for (int o = 1; o < 32; o <<= 1) {
            int n = __shfl_up_sync(0xffffffffu, incl, o);
            if (lane >= o) incl += n;
        }
        int excl  = incl - cnt;
        int total = __shfl_sync(0xffffffffu, incl, 31);
        int base  = 0;
        if (total > 0) {
            if (lane == 0) base = atomicAdd(&g_c1[b0], total);
            base = __shfl_sync(0xffffffffu, base, 0);
        }
        if (cnt > 0) {
            int w = base + excl;
            size_t batchBase4 = (size_t)b0 * V4_PER_BATCH;
#pragma unroll
            for (int k = 0; k < 8; k++) {
                float a[4] = {v[k].x, v[k].y, v[k].z, v[k].w};
                size_t idx4 = blockBase + (size_t)k * 256 + (tid & 255);
#pragma unroll
                for (int c = 0; c < 4; c++) {
                    if (a[c] > T0) {
                        unsigned flat = (unsigned)((idx4 - batchBase4) * 4 + c);
                        unsigned sb = __float_as_uint(a[c]);
                        if (w < CAP1)
                            g_cand1[b0][w] = ((unsigned long long)sb << 32) |
                                             (unsigned long long)(0xFFFFFFFFu - flat);
                        w++;
                    }
                }
            }
        }
    } else {
#pragma unroll
        for (int k = 0; k < 8; k++) {
            float a[4] = {v[k].x, v[k].y, v[k].z, v[k].w};
            size_t idx4 = blockBase + (size_t)k * 256 + (tid & 255);
            int be = (int)(idx4 / V4_PER_BATCH);
#pragma unroll
            for (int c = 0; c < 4; c++) {
                if (a[c] > T0) {
                    unsigned flat = (unsigned)((idx4 - (size_t)be * V4_PER_BATCH) * 4 + c);
                    unsigned sb = __float_as_uint(a[c]);
                    int pos = atomicAdd(&g_c1[be], 1);
                    if (pos < CAP1)
                        g_cand1[be][pos] = ((unsigned long long)sb << 32) |
                                           (unsigned long long)(0xFFFFFFFFu - flat);
                }
            }
        }
    }
}

__device__ __forceinline__ int fine_bucket(float s) {
    int bk = (int)((s - 0.95f) * 40960.0f);     // [0.95, 1.0] -> [0, 2047]
    if (bk < 0) bk = 0; if (bk > 2047) bk = 2047;
    return bk;
}

// ---------------- single persistent kernel ----------------------------------
__global__ void __launch_bounds__(1024) k_all(const float* __restrict__ boxes,
                                              const float* __restrict__ scores,
                                              float* __restrict__ out) {
    extern __shared__ char dyn[];
    unsigned long long* slotK = (unsigned long long*)(dyn + SM_SLOT);
    unsigned long long* sortK = (unsigned long long*)(dyn + SM_SORT);
    unsigned int* cntA   = (unsigned int*)(dyn + SM_CNT);
    unsigned int* startA = (unsigned int*)(dyn + SM_START);
    unsigned int* fillA  = (unsigned int*)(dyn + SM_FILL);
    float* sy1 = (float*)(dyn + SM_Y1);
    float* sx1 = (float*)(dyn + SM_X1);
    float* sy2 = (float*)(dyn + SM_Y2);
    float* sx2 = (float*)(dyn + SM_X2);
    float* sa  = (float*)(dyn + SM_AREA);
    int* clsCnt  = (int*)(dyn + SM_CLSCNT);
    int* clsOff  = (int*)(dyn + SM_CLSOFF);
    int* clsFill = (int*)(dyn + SM_CLSFILL);
    unsigned short* clsList = (unsigned short*)(dyn + SM_CLSLIST);
    volatile unsigned char* aliveArr = (volatile unsigned char*)(dyn + SM_ALIVE);
    unsigned int* wscan = (unsigned int*)(dyn + SM_WSCAN);

    __shared__ int sPiv;
    __shared__ int sCnt;
    __shared__ unsigned int skeep[32];
    __shared__ unsigned int warpTot[32];
    __shared__ unsigned int warpOff[32];
    __shared__ unsigned int sTotal;

    int tid = threadIdx.x;
    int w = tid >> 5, lane = tid & 31;

    // ================= phase 1: full-chip score scan =========================
    {
        const float4* p = (const float4*)scores;
        int grp = tid >> 8;                      // 0..3: four 256-thread groups
        for (int bb = blockIdx.x * 4 + grp; bb < SCAN_BLOCKS; bb += GRID * 4)
            scan_block(p, bb, tid, lane);
    }

    // ================= device-wide sense-reversing barrier ===================
    __syncthreads();
    if (tid == 0) {
        __threadfence();
        unsigned gen = g_gen;
        unsigned a = atomicAdd(&g_arrive, 1u);
        if (a == (unsigned)(gridDim.x - 1)) {
            g_arrive = 0;
            __threadfence();
            atomicAdd((unsigned*)&g_gen, 1u);
        } else {
            while (g_gen == gen) __nanosleep(64);
        }
        __threadfence();
    }
    __syncthreads();

    if (blockIdx.x >= BATCH) return;
    int b = blockIdx.x;

    // ================= phase 2: select + per-class NMS + output ==============
    int cRaw = g_c1[b];
    int c = cRaw; if (c > CAP1) c = CAP1;

    // ---- guarded fallback (never taken for this distribution) ----
    if (cRaw < TOPK || cRaw > CAP1) {
        unsigned int* hist4096 = cntA;           // cnt+start regions are contiguous
        for (int i = tid; i < 4096; i += 1024) hist4096[i] = 0u;
        if (tid == 0) sCnt = 0;
        __syncthreads();
        const float* sc = scores + (size_t)b * NC;
        for (int i = tid; i < NC; i += 1024) {
            float s = sc[i];
            if (s > SCORE_T) {
                int bk = (int)(s * 4096.0f); if (bk > 4095) bk = 4095;
                atomicAdd(&hist4096[bk], 1u);
            }
        }
        __syncthreads();
        if (tid == 0) {
            unsigned acc = 0; int piv = 0;
            for (int k = 4095; k >= 0; k--) { acc += hist4096[k]; if (acc >= TOPK) { piv = k; break; } }
            sPiv = piv;
        }
        __syncthreads();
        int piv = sPiv;
        for (int i = tid; i < NC; i += 1024) {
            float s = sc[i];
            if (s > SCORE_T) {
                int bk = (int)(s * 4096.0f); if (bk > 4095) bk = 4095;
                if (bk >= piv) {
                    int pos = atomicAdd(&sCnt, 1);
                    if (pos < CAP1) {
                        unsigned sb = __float_as_uint(s);
                        g_cand1[b][pos] = ((unsigned long long)sb << 32) |
                                          (unsigned long long)(0xFFFFFFFFu - (unsigned)i);
                    }
                }
            }
        }
        __syncthreads();
        c = sCnt; if (c > CAP1) c = CAP1;
    }

    // ---- zero scaffolding ----
    for (int i = tid; i < 2048; i += 1024) { cntA[i] = 0u; fillA[i] = 0u; }
    sortK[tid] = 0ull;
    if (tid < NCLS) { clsCnt[tid] = 0; clsFill[tid] = 0; }
    __syncthreads();

    // ---- counting sort: hist -> desc prefix -> scatter -> in-bucket rank ----
    for (int i = tid; i < c; i += 1024) {
        float s = __uint_as_float((unsigned)(g_cand1[b][i] >> 32));
        atomicAdd(&cntA[fine_bucket(s)], 1u);
    }
    __syncthreads();

    {   // descending exclusive prefix: start[bk] = sum cnt over buckets > bk
        unsigned c0  = cntA[2047 - 2 * tid];
        unsigned c1v = cntA[2047 - (2 * tid + 1)];
        unsigned psum = c0 + c1v;
        unsigned incl = psum;
#pragma unroll
        for (int o = 1; o < 32; o <<= 1) {
            unsigned n = __shfl_up_sync(0xffffffffu, incl, o);
            if (lane >= o) incl += n;
        }
        if (lane == 31) wscan[w] = incl;
        __syncthreads();
        if (w == 0) {
            unsigned v = wscan[lane];
            unsigned i2 = v;
#pragma unroll
            for (int o = 1; o < 32; o <<= 1) {
                unsigned n = __shfl_up_sync(0xffffffffu, i2, o);
                if (lane >= o) i2 += n;
            }
            wscan[lane] = i2 - v;
        }
        __syncthreads();
        unsigned base = wscan[w] + (incl - psum);
        startA[2047 - 2 * tid] = base;
        startA[2047 - (2 * tid + 1)] = base + c0;
    }
    __syncthreads();

    for (int i = tid; i < c; i += 1024) {
        unsigned long long key = g_cand1[b][i];
        float s = __uint_as_float((unsigned)(key >> 32));
        int bk = fine_bucket(s);
        unsigned pos = startA[bk] + atomicAdd(&fillA[bk], 1u);
        if (pos < CAP) slotK[pos] = key;
    }
    __syncthreads();

    {
        int Nw = c < CAP ? c : CAP;      // written slots are exactly [0, Nw)
        for (int t = tid; t < Nw; t += 1024) {
            unsigned long long key = slotK[t];
            float s = __uint_as_float((unsigned)(key >> 32));
            int bk = fine_bucket(s);
            unsigned lo = startA[bk];
            unsigned hi = lo + cntA[bk]; if (hi > (unsigned)CAP) hi = CAP;
            unsigned r = lo;
            for (unsigned q = lo; q < hi; q++)
                r += (slotK[q] > key) ? 1u : 0u;
            if (r < TOPK) sortK[r] = key;
        }
    }
    __syncthreads();

    // ---- gather: thread t owns sorted item t --------------------------------
    float myScore, bc0, bc1, bc2, bc3;
    int   myCls;
    {
        unsigned long long key = sortK[tid];
        float s = __uint_as_float((unsigned)(key >> 32));
        unsigned flat = 0xFFFFFFFFu - (unsigned)(key & 0xFFFFFFFFull);
        if (key == 0ull) { s = 0.0f; flat = 0u; }
        int bx = (int)(flat / NCLS), cl = (int)(flat % NCLS);
        const float4 bp = ((const float4*)boxes)[(size_t)b * NBOX + bx];
        bc0 = bp.x; bc1 = bp.y; bc2 = bp.z; bc3 = bp.w;
        float off = (float)cl * 4096.0f;
        float o0 = bc0 + off, o1 = bc1 + off, o2 = bc2 + off, o3 = bc3 + off;
        float area = ((o3 - o1) + 1.0f) * ((o2 - o0) + 1.0f);
        myScore = s; myCls = cl;
        sy1[tid] = o0; sx1[tid] = o1; sy2[tid] = o2; sx2[tid] = o3; sa[tid] = area;
        aliveArr[tid] = (s > SCORE_T) ? 1 : 0;
        atomicAdd(&clsCnt[cl], 1);
    }
    __syncthreads();

    // ---- class offsets ----
    if (tid == 0) {
        int acc = 0;
        for (int cc = 0; cc < NCLS; cc++) { clsOff[cc] = acc; acc += clsCnt[cc]; }
    }
    __syncthreads();

    // ---- build class lists in ascending tid (= descending score) order -----
    // 32 rounds, one warp per round; within a round, __match_any groups by class
    // and ranks by lane order, so overall order is exact tid order.
    for (int g = 0; g < 32; g++) {
        if (w == g) {
            unsigned mm = __match_any_sync(0xffffffffu, myCls);
            int lead = __ffs(mm) - 1;
            int rk = __popc(mm & ((1u << lane) - 1u));
            int basepos = 0;
            if (lane == lead) {
                basepos = clsFill[myCls];
                clsFill[myCls] = basepos + __popc(mm);   // distinct class per leader: no race
            }
            basepos = __shfl_sync(0xffffffffu, basepos, lead);
            clsList[clsOff[myCls] + basepos + rk] = (unsigned short)tid;
        }
        __syncthreads();
    }

    // ---- per-class greedy NMS: one warp per class (cross-class IoU == 0) ----
    for (int cc = w; cc < NCLS; cc += 32) {
        int base = clsOff[cc];
        int n = clsCnt[cc];
        for (int i = 0; i < n; i++) {
            int ti = clsList[base + i];
            if (aliveArr[ti]) {                       // lane-uniform read
                float iy1 = sy1[ti], ix1 = sx1[ti], iy2 = sy2[ti], ix2 = sx2[ti], ia = sa[ti];
                for (int j0 = i + 1 + lane; j0 < n; j0 += 32) {
                    int tj = clsList[base + j0];
                    if (aliveArr[tj]) {
                        float yy1 = fmaxf(iy1, sy1[tj]);
                        float xx1 = fmaxf(ix1, sx1[tj]);
                        float yy2 = fminf(iy2, sy2[tj]);
                        float xx2 = fminf(ix2, sx2[tj]);
                        float wd = fmaxf(0.0f, (xx2 - xx1) + 1.0f);
                        float ht = fmaxf(0.0f, (yy2 - yy1) + 1.0f);
                        float inter = wd * ht;
                        float uni = (ia + sa[tj]) - inter;
                        if (inter > IOU_T * uni) aliveArr[tj] = 0;
                    }
                }
            }
            __syncwarp();
        }
    }
    __syncthreads();

    // ---- stable partition + outputs ----------------------------------------
    bool keep = aliveArr[tid] != 0;
    unsigned bal = __ballot_sync(0xffffffffu, keep);
    if (lane == 0) { skeep[w] = bal; warpTot[w] = __popc(bal); }
    __syncthreads();
    if (tid == 0) {
        unsigned acc = 0;
        for (int i = 0; i < 32; i++) { warpOff[i] = acc; acc += warpTot[i]; }
        sTotal = acc;
    }
    __syncthreads();

    unsigned kwword = skeep[w];
    unsigned keptBefore = warpOff[w] + __popc(kwword & ((1u << lane) - 1u));
    unsigned total = sTotal;
    unsigned pos = keep ? keptBefore : (total + ((unsigned)tid - keptBefore));

    const int OFF_SCORES = BATCH * MAXDET * 4;
    const int OFF_LABELS = OFF_SCORES + BATCH * MAXDET;
    const int OFF_NVALID = OFF_LABELS + BATCH * MAXDET;

    if (pos < MAXDET) {
        float* ob = out + ((size_t)b * MAXDET + pos) * 4;
        ob[0] = bc0; ob[1] = bc1; ob[2] = bc2; ob[3] = bc3;
        out[OFF_SCORES + b * MAXDET + (int)pos] = keep ? myScore : 0.0f;
        out[OFF_LABELS + b * MAXDET + (int)pos] = (float)myCls;
    }
    if (tid == 0) {
        unsigned nv = total; if (nv > MAXDET) nv = MAXDET;
        out[OFF_NVALID + b] = (float)nv;
        g_c1[b] = 0;   // reset for next graph replay
    }
}

// ---------------- launch -----------------------------------------------------
extern "C" void kernel_launch(void* const* d_in, const int* in_sizes, int n_in,
                              void* d_out, int out_size) {
    (void)n_in; (void)out_size;
    const float* boxes;
    const float* scores;
    if (in_sizes[0] == BATCH * NBOX * 4) {
        boxes  = (const float*)d_in[0];
        scores = (const float*)d_in[1];
    } else {
        boxes  = (const float*)d_in[1];
        scores = (const float*)d_in[0];
    }

    cudaFuncSetAttribute(k_all, cudaFuncAttributeMaxDynamicSharedMemorySize, SM_TOTAL);

    k_all<<<GRID, 1024, SM_TOTAL>>>(boxes, scores, (float*)d_out);
}